// round 12
// baseline (speedup 1.0000x reference)
#include <cuda_runtime.h>
#include <cstdint>
#include <cstddef>

// Problem dims
#define T_STEPS 256
#define B_DIM   512
#define E_DIM   256
#define A_DIM   7
#define M_DIM   200
#define S_DIM   30
#define H_DIM   200
#define EA_DIM  263
#define G3      600
#define TB      131072   // T*B

typedef unsigned long long ull;

// Scratch (static device arrays: allocation-free rule)
__device__ float g_X[(size_t)TB * 200];   // X, later reused as P1
__device__ float g_GX[(size_t)TB * 600];  // precomputed input-side GRU gates
__device__ unsigned int g_flags[128];     // per-block epoch flags (scan barrier)

__device__ __forceinline__ float elu_f(float x) { return x > 0.f ? x : expm1f(x); }
__device__ __forceinline__ float sigm_f(float x) { return 1.f / (1.f + expf(-x)); }

// Packed f32x2 helpers (Blackwell FFMA2)
__device__ __forceinline__ void fma2(ull& d, ull a, ull b) {
    asm("fma.rn.f32x2 %0, %1, %2, %3;" : "=l"(d) : "l"(a), "l"(b), "l"(d));
}
__device__ __forceinline__ ull pack2(float x, float y) {
    ull r;
    asm("mov.b64 %0, {%1, %2};" : "=l"(r)
        : "r"(__float_as_uint(x)), "r"(__float_as_uint(y)));
    return r;
}
__device__ __forceinline__ void unpack2(ull v, float& lo, float& hi) {
    unsigned int a, b;
    asm("mov.b64 {%0, %1}, %2;" : "=r"(a), "=r"(b) : "l"(v));
    lo = __uint_as_float(a); hi = __uint_as_float(b);
}

// ---------------------------------------------------------------------------
// f32x2 tiled GEMM v2b: BM=128, BN=64, BK=16, 256 threads, double-buffered
// smem (as R10) + PRE-PACKED W smem: Ws2 holds (w,w) f32x2 pairs built once
// at fill time, removing the 4 MOV packs per kk from the hot loop.
// Inner loop per kk: 16 FFMA2 + 4 LDS.64 (A) + 2 LDS.128 (W).
// ---------------------------------------------------------------------------
#define GBM 128
#define GBN 64
#define GBK 16
#define ASTR 132                 // A row stride (floats)
#define WSTR2 66                 // W row stride (ull, packed pairs): 64 + 2 pad

template<int CONCAT>
__device__ __forceinline__ float4 loadA4(const float* __restrict__ A,
                                         const float* __restrict__ A2,
                                         size_t row, int k, int K, int KS)
{
    float4 v = make_float4(0.f, 0.f, 0.f, 0.f);
    if (CONCAT) {
        if (k + 3 < KS) {
            v = *(const float4*)(A + row * (size_t)KS + k);
        } else {
            float* pv = (float*)&v;
#pragma unroll
            for (int c = 0; c < 4; c++) {
                int kk = k + c;
                if (kk < KS)      pv[c] = A[row * (size_t)KS + kk];
                else if (kk < K)  pv[c] = A2[row * (size_t)(K - KS) + (kk - KS)];
            }
        }
    } else {
        if (k + 3 < K) {
            v = *(const float4*)(A + row * (size_t)K + k);
        } else {
            float* pv = (float*)&v;
#pragma unroll
            for (int c = 0; c < 4; c++)
                if (k + c < K) pv[c] = A[row * (size_t)K + k + c];
        }
    }
    return v;
}

__device__ __forceinline__ float4 loadW4(const float* __restrict__ W,
                                         int gn, int k, int K, int N)
{
    float4 v = make_float4(0.f, 0.f, 0.f, 0.f);
    if (gn < N) {
        if ((K & 3) == 0 && k + 3 < K) {
            v = *(const float4*)(W + (size_t)gn * (size_t)K + k);
        } else {
            float* pv = (float*)&v;
#pragma unroll
            for (int c = 0; c < 4; c++)
                if (k + c < K) pv[c] = W[(size_t)gn * (size_t)K + k + c];
        }
    }
    return v;
}

template<int ACT, int CONCAT>
__global__ __launch_bounds__(256, 2) void gemm_kernel(
    const float* __restrict__ A, const float* __restrict__ A2,
    int K, int KS,
    const float* __restrict__ W, const float* __restrict__ bias,
    float* __restrict__ C, int N)
{
    __shared__ float As[2][GBK * ASTR];      // As [s][kk][r]  (transposed)
    __shared__ ull   Ws2[2][GBK * WSTR2];    // Ws2[s][kk][n]  packed (w,w)

    const int row0 = blockIdx.x * GBM;
    const int col0 = blockIdx.y * GBN;
    const int tid = threadIdx.x;
    const int tx = tid & 15;     // 4 cols each
    const int ty = tid >> 4;     // 8 rows each (4 row-pairs)
    const int kq = tid & 3;      // loader: k-quad
    const int rA = tid >> 2;     // loader: 0..63

    ull acc[4][4];
#pragma unroll
    for (int i = 0; i < 4; i++)
#pragma unroll
        for (int j = 0; j < 4; j++) acc[i][j] = 0ull;

    float4 la0, la1, lw;
    const int nT = (K + GBK - 1) / GBK;

    // Prologue: tile 0 -> buffer 0
    la0 = loadA4<CONCAT>(A, A2, (size_t)(row0 + rA),      kq * 4, K, KS);
    la1 = loadA4<CONCAT>(A, A2, (size_t)(row0 + rA + 64), kq * 4, K, KS);
    lw  = loadW4(W, col0 + rA, kq * 4, K, N);
    {
        As[0][(kq * 4 + 0) * ASTR + rA]      = la0.x;
        As[0][(kq * 4 + 1) * ASTR + rA]      = la0.y;
        As[0][(kq * 4 + 2) * ASTR + rA]      = la0.z;
        As[0][(kq * 4 + 3) * ASTR + rA]      = la0.w;
        As[0][(kq * 4 + 0) * ASTR + rA + 64] = la1.x;
        As[0][(kq * 4 + 1) * ASTR + rA + 64] = la1.y;
        As[0][(kq * 4 + 2) * ASTR + rA + 64] = la1.z;
        As[0][(kq * 4 + 3) * ASTR + rA + 64] = la1.w;
        Ws2[0][(kq * 4 + 0) * WSTR2 + rA] = pack2(lw.x, lw.x);
        Ws2[0][(kq * 4 + 1) * WSTR2 + rA] = pack2(lw.y, lw.y);
        Ws2[0][(kq * 4 + 2) * WSTR2 + rA] = pack2(lw.z, lw.z);
        Ws2[0][(kq * 4 + 3) * WSTR2 + rA] = pack2(lw.w, lw.w);
    }
    __syncthreads();

    int p = 0;
    for (int t = 0; t < nT; t++) {
        // Issue LDGs for next tile first (compute below hides their latency)
        if (t + 1 < nT) {
            int k = (t + 1) * GBK + kq * 4;
            la0 = loadA4<CONCAT>(A, A2, (size_t)(row0 + rA),      k, K, KS);
            la1 = loadA4<CONCAT>(A, A2, (size_t)(row0 + rA + 64), k, K, KS);
            lw  = loadW4(W, col0 + rA, k, K, N);
        }

        // Compute on buffer p
        const float* Ab = As[p];
        const ull*   Wb = Ws2[p];
#pragma unroll
        for (int kk = 0; kk < GBK; kk++) {
            const ull* ap = (const ull*)(Ab + kk * ASTR + ty * 8);
            ull a2[4];
#pragma unroll
            for (int i = 0; i < 4; i++) a2[i] = ap[i];
            const ull* wp = Wb + kk * WSTR2 + tx * 4;
            ull w2[4];
#pragma unroll
            for (int j = 0; j < 4; j++) w2[j] = wp[j];
#pragma unroll
            for (int i = 0; i < 4; i++)
#pragma unroll
                for (int j = 0; j < 4; j++) fma2(acc[i][j], a2[i], w2[j]);
        }

        // Store next tile into the other buffer
        if (t + 1 < nT) {
            int s = p ^ 1;
            As[s][(kq * 4 + 0) * ASTR + rA]      = la0.x;
            As[s][(kq * 4 + 1) * ASTR + rA]      = la0.y;
            As[s][(kq * 4 + 2) * ASTR + rA]      = la0.z;
            As[s][(kq * 4 + 3) * ASTR + rA]      = la0.w;
            As[s][(kq * 4 + 0) * ASTR + rA + 64] = la1.x;
            As[s][(kq * 4 + 1) * ASTR + rA + 64] = la1.y;
            As[s][(kq * 4 + 2) * ASTR + rA + 64] = la1.z;
            As[s][(kq * 4 + 3) * ASTR + rA + 64] = la1.w;
            Ws2[s][(kq * 4 + 0) * WSTR2 + rA] = pack2(lw.x, lw.x);
            Ws2[s][(kq * 4 + 1) * WSTR2 + rA] = pack2(lw.y, lw.y);
            Ws2[s][(kq * 4 + 2) * WSTR2 + rA] = pack2(lw.z, lw.z);
            Ws2[s][(kq * 4 + 3) * WSTR2 + rA] = pack2(lw.w, lw.w);
            __syncthreads();
        }
        p ^= 1;
    }

    // Epilogue: bias + activation + vectorized stores
    const int gc0 = col0 + tx * 4;
    float bv[4];
#pragma unroll
    for (int j = 0; j < 4; j++) bv[j] = (gc0 + j < N) ? bias[gc0 + j] : 0.f;

#pragma unroll
    for (int i = 0; i < 4; i++) {
        float vlo[4], vhi[4];
#pragma unroll
        for (int j = 0; j < 4; j++) {
            float lo, hi;
            unpack2(acc[i][j], lo, hi);
            lo += bv[j]; hi += bv[j];
            if (ACT) { lo = elu_f(lo); hi = elu_f(hi); }
            vlo[j] = lo; vhi[j] = hi;
        }
        size_t gr0 = (size_t)(row0 + ty * 8 + 2 * i);
        if (gc0 + 3 < N) {
            *(float4*)(C + gr0 * (size_t)N + gc0)       = make_float4(vlo[0], vlo[1], vlo[2], vlo[3]);
            *(float4*)(C + (gr0 + 1) * (size_t)N + gc0) = make_float4(vhi[0], vhi[1], vhi[2], vhi[3]);
        } else {
#pragma unroll
            for (int j = 0; j < 4; j++) {
                if (gc0 + j < N) {
                    C[gr0 * (size_t)N + gc0 + j]       = vlo[j];
                    C[(gr0 + 1) * (size_t)N + gc0 + j] = vhi[j];
                }
            }
        }
    }
}

// ---------------------------------------------------------------------------
// Recurrent scan v2 (unchanged from R10).
// ---------------------------------------------------------------------------
#define SC_C   8
#define SC_R   16
#define SC_MC  25
#define SC_BC  32
#define SC_ROWS  75
#define SC_ROWSP 80
#define SC_HSTR  202
#define SC_GSTR  34
#define SC_THREADS 256
#define SC_SMEM_FLOATS (SC_ROWSP*200 + SC_BC*SC_HSTR + SC_ROWSP*SC_GSTR + G3)

__global__ void init_flags_kernel() { g_flags[threadIdx.x] = 0u; }

__global__ __launch_bounds__(SC_THREADS) void scan_kernel(
    const float* __restrict__ GX, const float* __restrict__ Whh,
    const float* __restrict__ bhh, const float* __restrict__ in_state,
    const unsigned char* __restrict__ reset, float* __restrict__ states)
{
    extern __shared__ float sm[];
    float* sW  = sm;                            // [80][200]  Whh slice
    float* sH  = sW + SC_ROWSP * 200;           // [32][202]  h (stride 202)
    float* sGH = sH + SC_BC * SC_HSTR;          // [80][34]   gh results
    float* sBH = sGH + SC_ROWSP * SC_GSTR;      // [600]      bhh

    const int c   = blockIdx.x & 7;
    const int r   = blockIdx.x >> 3;
    const int tid = threadIdx.x;
    const int rg  = tid >> 4;   // 0..15 -> 5 gh-rows each
    const int bg  = tid & 15;   // 0..15 -> 2 batch cols each

    for (int idx = tid; idx < SC_ROWSP * 200; idx += SC_THREADS) {
        int lr = idx / 200, k = idx % 200;
        float v = 0.f;
        if (lr < SC_ROWS) {
            int g = lr / SC_MC, j = lr % SC_MC;
            int grow = g * 200 + c * SC_MC + j;
            v = Whh[(size_t)grow * 200 + k];
        }
        sW[idx] = v;
    }
    for (int idx = tid; idx < G3; idx += SC_THREADS) sBH[idx] = bhh[idx];

    float pxr[4], pxz[4], pxn[4];
#pragma unroll
    for (int q = 0; q < 4; q++) {
        int idx = tid + q * SC_THREADS;
        if (idx < SC_MC * SC_BC) {
            int bl = idx / SC_MC, j = idx % SC_MC;
            int b = r * SC_BC + bl;
            int m = c * SC_MC + j;
            size_t gxi = (size_t)b * G3 + m;
            pxr[q] = GX[gxi];
            pxz[q] = GX[gxi + 200];
            pxn[q] = GX[gxi + 400];
        } else { pxr[q] = pxz[q] = pxn[q] = 0.f; }
    }

    for (int t = 0; t < T_STEPS; t++) {
        const float* hsrc = (t == 0) ? in_state
                                     : (states + (size_t)(t - 1) * B_DIM * M_DIM);
        for (int idx = tid; idx < SC_BC * 100; idx += SC_THREADS) {
            int bl = idx / 100, kp = idx % 100;
            int b = r * SC_BC + bl;
            ull v = *(const ull*)(hsrc + (size_t)b * 200 + kp * 2);
            if (reset[t * B_DIM + b]) v = 0ull;
            *(ull*)(sH + bl * SC_HSTR + kp * 2) = v;
        }
        __syncthreads();

        ull acc[5][2];
#pragma unroll
        for (int i = 0; i < 5; i++) { acc[i][0] = 0ull; acc[i][1] = 0ull; }

        const float* hb0 = sH + (bg * 2) * SC_HSTR;
        const float* hb1 = hb0 + SC_HSTR;
#pragma unroll 2
        for (int k = 0; k < 200; k += 4) {
            ull w0[5], w1[5];
#pragma unroll
            for (int i = 0; i < 5; i++) {
                const ull* wp = (const ull*)(sW + (rg * 5 + i) * 200 + k);
                w0[i] = wp[0]; w1[i] = wp[1];
            }
            ull h00 = *(const ull*)(hb0 + k);
            ull h01 = *(const ull*)(hb0 + k + 2);
            ull h10 = *(const ull*)(hb1 + k);
            ull h11 = *(const ull*)(hb1 + k + 2);
#pragma unroll
            for (int i = 0; i < 5; i++) {
                fma2(acc[i][0], w0[i], h00);
                fma2(acc[i][0], w1[i], h01);
                fma2(acc[i][1], w0[i], h10);
                fma2(acc[i][1], w1[i], h11);
            }
        }
#pragma unroll
        for (int i = 0; i < 5; i++) {
            float l0, h0, l1, h1;
            unpack2(acc[i][0], l0, h0);
            unpack2(acc[i][1], l1, h1);
            *(ull*)(sGH + (rg * 5 + i) * SC_GSTR + bg * 2) =
                pack2(l0 + h0, l1 + h1);
        }
        __syncthreads();

#pragma unroll
        for (int q = 0; q < 4; q++) {
            int idx = tid + q * SC_THREADS;
            if (idx < SC_MC * SC_BC) {
                int bl = idx / SC_MC, j = idx % SC_MC;
                int b = r * SC_BC + bl;
                int m = c * SC_MC + j;
                float hr = sGH[j * SC_GSTR + bl]               + sBH[m];
                float hz = sGH[(SC_MC + j) * SC_GSTR + bl]     + sBH[200 + m];
                float hn = sGH[(2 * SC_MC + j) * SC_GSTR + bl] + sBH[400 + m];
                float rgate = sigm_f(pxr[q] + hr);
                float z     = sigm_f(pxz[q] + hz);
                float n     = tanhf(pxn[q] + rgate * hn);
                float hp    = sH[bl * SC_HSTR + m];
                float hnew  = (1.f - z) * n + z * hp;
                states[(size_t)t * B_DIM * M_DIM + (size_t)b * M_DIM + m] = hnew;
            }
        }

        if (t + 1 < T_STEPS) {
            __syncthreads();
            if (tid == 0) {
                asm volatile("st.release.gpu.global.u32 [%0], %1;"
                             :: "l"(g_flags + blockIdx.x), "r"((unsigned)(t + 1))
                             : "memory");
            }
            size_t gbase = (size_t)((t + 1) * B_DIM) * G3;
#pragma unroll
            for (int q = 0; q < 4; q++) {
                int idx = tid + q * SC_THREADS;
                if (idx < SC_MC * SC_BC) {
                    int bl = idx / SC_MC, j = idx % SC_MC;
                    int b = r * SC_BC + bl;
                    int m = c * SC_MC + j;
                    size_t gxi = gbase + (size_t)b * G3 + m;
                    pxr[q] = GX[gxi];
                    pxz[q] = GX[gxi + 200];
                    pxn[q] = GX[gxi + 400];
                }
            }
            if (tid < SC_C) {
                const unsigned int* fp = g_flags + (r << 3) + tid;
                unsigned int v;
                do {
                    asm volatile("ld.acquire.gpu.global.u32 %0, [%1];"
                                 : "=r"(v) : "l"(fp) : "memory");
                } while (v < (unsigned)(t + 1));
            }
            __syncthreads();
        }
    }
}

// ---------------------------------------------------------------------------
// Sample head: partitionable threefry (counter = linear index), bits = o0^o1.
// ---------------------------------------------------------------------------
__global__ void sample_kernel(const float* __restrict__ posts_last,
                              float* __restrict__ out)
{
    int i = blockIdx.x * blockDim.x + threadIdx.x;
    const int NTOT = B_DIM * S_DIM;
    if (i >= NTOT) return;

    uint32_t x0 = 0u, x1 = (uint32_t)i;
    const uint32_t ks0 = 0u, ks1 = 42u, ks2 = 0u ^ 42u ^ 0x1BD11BDAu;
    x0 += ks0; x1 += ks1;
#define TF_RND(rot) { x0 += x1; x1 = (x1 << (rot)) | (x1 >> (32 - (rot))); x1 ^= x0; }
    TF_RND(13) TF_RND(15) TF_RND(26) TF_RND(6)   x0 += ks1; x1 += ks2 + 1u;
    TF_RND(17) TF_RND(29) TF_RND(16) TF_RND(24)  x0 += ks2; x1 += ks0 + 2u;
    TF_RND(13) TF_RND(15) TF_RND(26) TF_RND(6)   x0 += ks0; x1 += ks1 + 3u;
    TF_RND(17) TF_RND(29) TF_RND(16) TF_RND(24)  x0 += ks1; x1 += ks2 + 4u;
    TF_RND(13) TF_RND(15) TF_RND(26) TF_RND(6)   x0 += ks2; x1 += ks0 + 5u;
#undef TF_RND
    uint32_t bits = x0 ^ x1;

    float f = __uint_as_float((bits >> 9) | 0x3F800000u) - 1.0f;
    const float lo = -0.99999994f;
    float u = fmaxf(lo, f * 2.0f + lo);
    float noise = 1.41421356f * erfinvf(u);

    int b = i / S_DIM, s = i % S_DIM;
    float mean = posts_last[(size_t)b * 60 + s];
    float sraw = posts_last[(size_t)b * 60 + 30 + s];
    float stdv = fmaxf(sraw, 0.f) + log1pf(expf(-fabsf(sraw))) + 0.1f;
    out[i] = mean + stdv * noise;
}

// ---------------------------------------------------------------------------
extern "C" void kernel_launch(void* const* d_in, const int* in_sizes, int n_in,
                              void* d_out, int out_size)
{
    const float* embed    = (const float*)d_in[0];
    const float* action   = (const float*)d_in[1];
    const unsigned char* reset = (const unsigned char*)d_in[2];
    const float* in_state = (const float*)d_in[3];
    const float* W1 = (const float*)d_in[4];
    const float* b1 = (const float*)d_in[5];
    const float *Wih, *bih, *Whh, *bhh;
    if (in_sizes[7] == 600) {          // dict order: Wih, bih, Whh, bhh
        Wih = (const float*)d_in[6]; bih = (const float*)d_in[7];
        Whh = (const float*)d_in[8]; bhh = (const float*)d_in[9];
    } else {                           // signature order: Wih, Whh, bih, bhh
        Wih = (const float*)d_in[6]; Whh = (const float*)d_in[7];
        bih = (const float*)d_in[8]; bhh = (const float*)d_in[9];
    }
    const float* W2 = (const float*)d_in[10];
    const float* b2 = (const float*)d_in[11];
    const float* W3 = (const float*)d_in[12];
    const float* b3 = (const float*)d_in[13];

    float* out    = (float*)d_out;
    float* sample = out;                                  // [512,30]
    float* states = out + (size_t)B_DIM * S_DIM;          // [256,512,200]
    float* posts  = states + (size_t)T_STEPS * B_DIM * M_DIM; // [256,512,60]

    float* Xbuf; cudaGetSymbolAddress((void**)&Xbuf, g_X);
    float* GXbuf; cudaGetSymbolAddress((void**)&GXbuf, g_GX);

    // K1: X = elu([embed,action] @ W1^T + b1)   [131072,263]x[263,200]
    gemm_kernel<1, 1><<<dim3(TB / GBM, 4), 256>>>(
        embed, action, EA_DIM, E_DIM, W1, b1, Xbuf, H_DIM);

    // K2: GX = X @ Wih^T + bih                  [131072,200]x[200,600]
    gemm_kernel<0, 0><<<dim3(TB / GBM, 10), 256>>>(
        Xbuf, nullptr, H_DIM, 0, Wih, bih, GXbuf, G3);

    // K3: recurrent scan -> states
    init_flags_kernel<<<1, 128>>>();
    cudaFuncSetAttribute(scan_kernel,
                         cudaFuncAttributeMaxDynamicSharedMemorySize,
                         SC_SMEM_FLOATS * (int)sizeof(float));
    scan_kernel<<<SC_C * SC_R, SC_THREADS, SC_SMEM_FLOATS * sizeof(float)>>>(
        GXbuf, Whh, bhh, in_state, reset, states);

    // K4: P1 = elu(states @ W2^T + b2)  (reuse g_X)
    gemm_kernel<1, 0><<<dim3(TB / GBM, 4), 256>>>(
        states, nullptr, M_DIM, 0, W2, b2, Xbuf, H_DIM);

    // K5: posts = P1 @ W3^T + b3
    gemm_kernel<0, 0><<<dim3(TB / GBM, 1), 256>>>(
        Xbuf, nullptr, H_DIM, 0, W3, b3, posts, 2 * S_DIM);

    // K6: sample from posts[-1] with partitionable-threefry noise
    const float* posts_last = posts + (size_t)(T_STEPS - 1) * B_DIM * 2 * S_DIM;
    sample_kernel<<<(B_DIM * S_DIM + 255) / 256, 256>>>(posts_last, sample);
}

// round 13
// speedup vs baseline: 1.3283x; 1.3283x over previous
#include <cuda_runtime.h>
#include <cstdint>
#include <cstddef>

// Problem dims
#define T_STEPS 256
#define B_DIM   512
#define E_DIM   256
#define A_DIM   7
#define M_DIM   200
#define S_DIM   30
#define H_DIM   200
#define EA_DIM  263
#define G3      600
#define TB      131072   // T*B

typedef unsigned long long ull;

// Scratch (static device arrays: allocation-free rule)
__device__ float g_X[(size_t)TB * 200];   // X, later reused as P1
__device__ float g_GX[(size_t)TB * 600];  // precomputed input-side GRU gates
__device__ unsigned int g_flags[128];     // per-block epoch flags (scan barrier)

__device__ __forceinline__ float elu_f(float x) { return x > 0.f ? x : expm1f(x); }
__device__ __forceinline__ float sigm_f(float x) { return 1.f / (1.f + expf(-x)); }

// Packed f32x2 helpers
__device__ __forceinline__ void fma2(ull& d, ull a, ull b) {
    asm("fma.rn.f32x2 %0, %1, %2, %3;" : "=l"(d) : "l"(a), "l"(b), "l"(d));
}
__device__ __forceinline__ ull pack2(float x, float y) {
    ull r;
    asm("mov.b64 %0, {%1, %2};" : "=l"(r)
        : "r"(__float_as_uint(x)), "r"(__float_as_uint(y)));
    return r;
}
__device__ __forceinline__ void unpack2(ull v, float& lo, float& hi) {
    unsigned int a, b;
    asm("mov.b64 {%0, %1}, %2;" : "=r"(a), "=r"(b) : "l"(v));
    lo = __uint_as_float(a); hi = __uint_as_float(b);
}

// ---------------------------------------------------------------------------
// f32x2 tiled GEMM (R10 shape): BM=128, BN=64, BK=16, 256 threads, 2-stage
// smem double buffer, microtile 8 rows x 4 cols (f32x2 over row pairs).
// ONLY change vs R10: __launch_bounds__(256,3) -> 6 warps/SMSP to cover
// LDS/sync latency (GEMMs measured at 1.7x their FFMA floor with 4/SMSP).
// ---------------------------------------------------------------------------
#define GBM 128
#define GBN 64
#define GBK 16
#define ASTR 132
#define WSTR 68

template<int CONCAT>
__device__ __forceinline__ float4 loadA4(const float* __restrict__ A,
                                         const float* __restrict__ A2,
                                         size_t row, int k, int K, int KS)
{
    float4 v = make_float4(0.f, 0.f, 0.f, 0.f);
    if (CONCAT) {
        if (k + 3 < KS) {
            v = *(const float4*)(A + row * (size_t)KS + k);
        } else {
            float* pv = (float*)&v;
#pragma unroll
            for (int c = 0; c < 4; c++) {
                int kk = k + c;
                if (kk < KS)      pv[c] = A[row * (size_t)KS + kk];
                else if (kk < K)  pv[c] = A2[row * (size_t)(K - KS) + (kk - KS)];
            }
        }
    } else {
        if (k + 3 < K) {
            v = *(const float4*)(A + row * (size_t)K + k);
        } else {
            float* pv = (float*)&v;
#pragma unroll
            for (int c = 0; c < 4; c++)
                if (k + c < K) pv[c] = A[row * (size_t)K + k + c];
        }
    }
    return v;
}

__device__ __forceinline__ float4 loadW4(const float* __restrict__ W,
                                         int gn, int k, int K, int N)
{
    float4 v = make_float4(0.f, 0.f, 0.f, 0.f);
    if (gn < N) {
        if ((K & 3) == 0 && k + 3 < K) {
            v = *(const float4*)(W + (size_t)gn * (size_t)K + k);
        } else {
            float* pv = (float*)&v;
#pragma unroll
            for (int c = 0; c < 4; c++)
                if (k + c < K) pv[c] = W[(size_t)gn * (size_t)K + k + c];
        }
    }
    return v;
}

template<int ACT, int CONCAT>
__global__ __launch_bounds__(256, 3) void gemm_kernel(
    const float* __restrict__ A, const float* __restrict__ A2,
    int K, int KS,
    const float* __restrict__ W, const float* __restrict__ bias,
    float* __restrict__ C, int N)
{
    __shared__ float As[2][GBK * ASTR];
    __shared__ float Ws[2][GBK * WSTR];

    const int row0 = blockIdx.x * GBM;
    const int col0 = blockIdx.y * GBN;
    const int tid = threadIdx.x;
    const int tx = tid & 15;
    const int ty = tid >> 4;
    const int kq = tid & 3;
    const int rA = tid >> 2;

    ull acc[4][4];
#pragma unroll
    for (int i = 0; i < 4; i++)
#pragma unroll
        for (int j = 0; j < 4; j++) acc[i][j] = 0ull;

    float4 la0, la1, lw;
    const int nT = (K + GBK - 1) / GBK;

    la0 = loadA4<CONCAT>(A, A2, (size_t)(row0 + rA),      kq * 4, K, KS);
    la1 = loadA4<CONCAT>(A, A2, (size_t)(row0 + rA + 64), kq * 4, K, KS);
    lw  = loadW4(W, col0 + rA, kq * 4, K, N);
    {
        As[0][(kq * 4 + 0) * ASTR + rA]      = la0.x;
        As[0][(kq * 4 + 1) * ASTR + rA]      = la0.y;
        As[0][(kq * 4 + 2) * ASTR + rA]      = la0.z;
        As[0][(kq * 4 + 3) * ASTR + rA]      = la0.w;
        As[0][(kq * 4 + 0) * ASTR + rA + 64] = la1.x;
        As[0][(kq * 4 + 1) * ASTR + rA + 64] = la1.y;
        As[0][(kq * 4 + 2) * ASTR + rA + 64] = la1.z;
        As[0][(kq * 4 + 3) * ASTR + rA + 64] = la1.w;
        Ws[0][(kq * 4 + 0) * WSTR + rA] = lw.x;
        Ws[0][(kq * 4 + 1) * WSTR + rA] = lw.y;
        Ws[0][(kq * 4 + 2) * WSTR + rA] = lw.z;
        Ws[0][(kq * 4 + 3) * WSTR + rA] = lw.w;
    }
    __syncthreads();

    int p = 0;
    for (int t = 0; t < nT; t++) {
        if (t + 1 < nT) {
            int k = (t + 1) * GBK + kq * 4;
            la0 = loadA4<CONCAT>(A, A2, (size_t)(row0 + rA),      k, K, KS);
            la1 = loadA4<CONCAT>(A, A2, (size_t)(row0 + rA + 64), k, K, KS);
            lw  = loadW4(W, col0 + rA, k, K, N);
        }

        const float* Ab = As[p];
        const float* Wb = Ws[p];
#pragma unroll
        for (int kk = 0; kk < GBK; kk++) {
            const ull* ap = (const ull*)(Ab + kk * ASTR + ty * 8);
            ull a2[4];
#pragma unroll
            for (int i = 0; i < 4; i++) a2[i] = ap[i];
            const float4 wv = *(const float4*)(Wb + kk * WSTR + tx * 4);
            ull w2[4];
            w2[0] = pack2(wv.x, wv.x);
            w2[1] = pack2(wv.y, wv.y);
            w2[2] = pack2(wv.z, wv.z);
            w2[3] = pack2(wv.w, wv.w);
#pragma unroll
            for (int i = 0; i < 4; i++)
#pragma unroll
                for (int j = 0; j < 4; j++) fma2(acc[i][j], a2[i], w2[j]);
        }

        if (t + 1 < nT) {
            int s = p ^ 1;
            As[s][(kq * 4 + 0) * ASTR + rA]      = la0.x;
            As[s][(kq * 4 + 1) * ASTR + rA]      = la0.y;
            As[s][(kq * 4 + 2) * ASTR + rA]      = la0.z;
            As[s][(kq * 4 + 3) * ASTR + rA]      = la0.w;
            As[s][(kq * 4 + 0) * ASTR + rA + 64] = la1.x;
            As[s][(kq * 4 + 1) * ASTR + rA + 64] = la1.y;
            As[s][(kq * 4 + 2) * ASTR + rA + 64] = la1.z;
            As[s][(kq * 4 + 3) * ASTR + rA + 64] = la1.w;
            Ws[s][(kq * 4 + 0) * WSTR + rA] = lw.x;
            Ws[s][(kq * 4 + 1) * WSTR + rA] = lw.y;
            Ws[s][(kq * 4 + 2) * WSTR + rA] = lw.z;
            Ws[s][(kq * 4 + 3) * WSTR + rA] = lw.w;
            __syncthreads();
        }
        p ^= 1;
    }

    const int gc0 = col0 + tx * 4;
    float bv[4];
#pragma unroll
    for (int j = 0; j < 4; j++) bv[j] = (gc0 + j < N) ? bias[gc0 + j] : 0.f;

#pragma unroll
    for (int i = 0; i < 4; i++) {
        float vlo[4], vhi[4];
#pragma unroll
        for (int j = 0; j < 4; j++) {
            float lo, hi;
            unpack2(acc[i][j], lo, hi);
            lo += bv[j]; hi += bv[j];
            if (ACT) { lo = elu_f(lo); hi = elu_f(hi); }
            vlo[j] = lo; vhi[j] = hi;
        }
        size_t gr0 = (size_t)(row0 + ty * 8 + 2 * i);
        if (gc0 + 3 < N) {
            *(float4*)(C + gr0 * (size_t)N + gc0)       = make_float4(vlo[0], vlo[1], vlo[2], vlo[3]);
            *(float4*)(C + (gr0 + 1) * (size_t)N + gc0) = make_float4(vhi[0], vhi[1], vhi[2], vhi[3]);
        } else {
#pragma unroll
            for (int j = 0; j < 4; j++) {
                if (gc0 + j < N) {
                    C[gr0 * (size_t)N + gc0 + j]       = vlo[j];
                    C[(gr0 + 1) * (size_t)N + gc0 + j] = vhi[j];
                }
            }
        }
    }
}

// ---------------------------------------------------------------------------
// Recurrent scan v2 (unchanged from R10).
// ---------------------------------------------------------------------------
#define SC_C   8
#define SC_R   16
#define SC_MC  25
#define SC_BC  32
#define SC_ROWS  75
#define SC_ROWSP 80
#define SC_HSTR  202
#define SC_GSTR  34
#define SC_THREADS 256
#define SC_SMEM_FLOATS (SC_ROWSP*200 + SC_BC*SC_HSTR + SC_ROWSP*SC_GSTR + G3)

__global__ void init_flags_kernel() { g_flags[threadIdx.x] = 0u; }

__global__ __launch_bounds__(SC_THREADS) void scan_kernel(
    const float* __restrict__ GX, const float* __restrict__ Whh,
    const float* __restrict__ bhh, const float* __restrict__ in_state,
    const unsigned char* __restrict__ reset, float* __restrict__ states)
{
    extern __shared__ float sm[];
    float* sW  = sm;                            // [80][200]  Whh slice
    float* sH  = sW + SC_ROWSP * 200;           // [32][202]  h (stride 202)
    float* sGH = sH + SC_BC * SC_HSTR;          // [80][34]   gh results
    float* sBH = sGH + SC_ROWSP * SC_GSTR;      // [600]      bhh

    const int c   = blockIdx.x & 7;
    const int r   = blockIdx.x >> 3;
    const int tid = threadIdx.x;
    const int rg  = tid >> 4;   // 0..15 -> 5 gh-rows each
    const int bg  = tid & 15;   // 0..15 -> 2 batch cols each

    for (int idx = tid; idx < SC_ROWSP * 200; idx += SC_THREADS) {
        int lr = idx / 200, k = idx % 200;
        float v = 0.f;
        if (lr < SC_ROWS) {
            int g = lr / SC_MC, j = lr % SC_MC;
            int grow = g * 200 + c * SC_MC + j;
            v = Whh[(size_t)grow * 200 + k];
        }
        sW[idx] = v;
    }
    for (int idx = tid; idx < G3; idx += SC_THREADS) sBH[idx] = bhh[idx];

    float pxr[4], pxz[4], pxn[4];
#pragma unroll
    for (int q = 0; q < 4; q++) {
        int idx = tid + q * SC_THREADS;
        if (idx < SC_MC * SC_BC) {
            int bl = idx / SC_MC, j = idx % SC_MC;
            int b = r * SC_BC + bl;
            int m = c * SC_MC + j;
            size_t gxi = (size_t)b * G3 + m;
            pxr[q] = GX[gxi];
            pxz[q] = GX[gxi + 200];
            pxn[q] = GX[gxi + 400];
        } else { pxr[q] = pxz[q] = pxn[q] = 0.f; }
    }

    for (int t = 0; t < T_STEPS; t++) {
        const float* hsrc = (t == 0) ? in_state
                                     : (states + (size_t)(t - 1) * B_DIM * M_DIM);
        for (int idx = tid; idx < SC_BC * 100; idx += SC_THREADS) {
            int bl = idx / 100, kp = idx % 100;
            int b = r * SC_BC + bl;
            ull v = *(const ull*)(hsrc + (size_t)b * 200 + kp * 2);
            if (reset[t * B_DIM + b]) v = 0ull;
            *(ull*)(sH + bl * SC_HSTR + kp * 2) = v;
        }
        __syncthreads();

        ull acc[5][2];
#pragma unroll
        for (int i = 0; i < 5; i++) { acc[i][0] = 0ull; acc[i][1] = 0ull; }

        const float* hb0 = sH + (bg * 2) * SC_HSTR;
        const float* hb1 = hb0 + SC_HSTR;
#pragma unroll 2
        for (int k = 0; k < 200; k += 4) {
            ull w0[5], w1[5];
#pragma unroll
            for (int i = 0; i < 5; i++) {
                const ull* wp = (const ull*)(sW + (rg * 5 + i) * 200 + k);
                w0[i] = wp[0]; w1[i] = wp[1];
            }
            ull h00 = *(const ull*)(hb0 + k);
            ull h01 = *(const ull*)(hb0 + k + 2);
            ull h10 = *(const ull*)(hb1 + k);
            ull h11 = *(const ull*)(hb1 + k + 2);
#pragma unroll
            for (int i = 0; i < 5; i++) {
                fma2(acc[i][0], w0[i], h00);
                fma2(acc[i][0], w1[i], h01);
                fma2(acc[i][1], w0[i], h10);
                fma2(acc[i][1], w1[i], h11);
            }
        }
#pragma unroll
        for (int i = 0; i < 5; i++) {
            float l0, h0, l1, h1;
            unpack2(acc[i][0], l0, h0);
            unpack2(acc[i][1], l1, h1);
            *(ull*)(sGH + (rg * 5 + i) * SC_GSTR + bg * 2) =
                pack2(l0 + h0, l1 + h1);
        }
        __syncthreads();

#pragma unroll
        for (int q = 0; q < 4; q++) {
            int idx = tid + q * SC_THREADS;
            if (idx < SC_MC * SC_BC) {
                int bl = idx / SC_MC, j = idx % SC_MC;
                int b = r * SC_BC + bl;
                int m = c * SC_MC + j;
                float hr = sGH[j * SC_GSTR + bl]               + sBH[m];
                float hz = sGH[(SC_MC + j) * SC_GSTR + bl]     + sBH[200 + m];
                float hn = sGH[(2 * SC_MC + j) * SC_GSTR + bl] + sBH[400 + m];
                float rgate = sigm_f(pxr[q] + hr);
                float z     = sigm_f(pxz[q] + hz);
                float n     = tanhf(pxn[q] + rgate * hn);
                float hp    = sH[bl * SC_HSTR + m];
                float hnew  = (1.f - z) * n + z * hp;
                states[(size_t)t * B_DIM * M_DIM + (size_t)b * M_DIM + m] = hnew;
            }
        }

        if (t + 1 < T_STEPS) {
            __syncthreads();
            if (tid == 0) {
                asm volatile("st.release.gpu.global.u32 [%0], %1;"
                             :: "l"(g_flags + blockIdx.x), "r"((unsigned)(t + 1))
                             : "memory");
            }
            size_t gbase = (size_t)((t + 1) * B_DIM) * G3;
#pragma unroll
            for (int q = 0; q < 4; q++) {
                int idx = tid + q * SC_THREADS;
                if (idx < SC_MC * SC_BC) {
                    int bl = idx / SC_MC, j = idx % SC_MC;
                    int b = r * SC_BC + bl;
                    int m = c * SC_MC + j;
                    size_t gxi = gbase + (size_t)b * G3 + m;
                    pxr[q] = GX[gxi];
                    pxz[q] = GX[gxi + 200];
                    pxn[q] = GX[gxi + 400];
                }
            }
            if (tid < SC_C) {
                const unsigned int* fp = g_flags + (r << 3) + tid;
                unsigned int v;
                do {
                    asm volatile("ld.acquire.gpu.global.u32 %0, [%1];"
                                 : "=r"(v) : "l"(fp) : "memory");
                } while (v < (unsigned)(t + 1));
            }
            __syncthreads();
        }
    }
}

// ---------------------------------------------------------------------------
// Sample head: partitionable threefry (counter = linear index), bits = o0^o1.
// ---------------------------------------------------------------------------
__global__ void sample_kernel(const float* __restrict__ posts_last,
                              float* __restrict__ out)
{
    int i = blockIdx.x * blockDim.x + threadIdx.x;
    const int NTOT = B_DIM * S_DIM;
    if (i >= NTOT) return;

    uint32_t x0 = 0u, x1 = (uint32_t)i;
    const uint32_t ks0 = 0u, ks1 = 42u, ks2 = 0u ^ 42u ^ 0x1BD11BDAu;
    x0 += ks0; x1 += ks1;
#define TF_RND(rot) { x0 += x1; x1 = (x1 << (rot)) | (x1 >> (32 - (rot))); x1 ^= x0; }
    TF_RND(13) TF_RND(15) TF_RND(26) TF_RND(6)   x0 += ks1; x1 += ks2 + 1u;
    TF_RND(17) TF_RND(29) TF_RND(16) TF_RND(24)  x0 += ks2; x1 += ks0 + 2u;
    TF_RND(13) TF_RND(15) TF_RND(26) TF_RND(6)   x0 += ks0; x1 += ks1 + 3u;
    TF_RND(17) TF_RND(29) TF_RND(16) TF_RND(24)  x0 += ks1; x1 += ks2 + 4u;
    TF_RND(13) TF_RND(15) TF_RND(26) TF_RND(6)   x0 += ks2; x1 += ks0 + 5u;
#undef TF_RND
    uint32_t bits = x0 ^ x1;

    float f = __uint_as_float((bits >> 9) | 0x3F800000u) - 1.0f;
    const float lo = -0.99999994f;
    float u = fmaxf(lo, f * 2.0f + lo);
    float noise = 1.41421356f * erfinvf(u);

    int b = i / S_DIM, s = i % S_DIM;
    float mean = posts_last[(size_t)b * 60 + s];
    float sraw = posts_last[(size_t)b * 60 + 30 + s];
    float stdv = fmaxf(sraw, 0.f) + log1pf(expf(-fabsf(sraw))) + 0.1f;
    out[i] = mean + stdv * noise;
}

// ---------------------------------------------------------------------------
extern "C" void kernel_launch(void* const* d_in, const int* in_sizes, int n_in,
                              void* d_out, int out_size)
{
    const float* embed    = (const float*)d_in[0];
    const float* action   = (const float*)d_in[1];
    const unsigned char* reset = (const unsigned char*)d_in[2];
    const float* in_state = (const float*)d_in[3];
    const float* W1 = (const float*)d_in[4];
    const float* b1 = (const float*)d_in[5];
    const float *Wih, *bih, *Whh, *bhh;
    if (in_sizes[7] == 600) {          // dict order: Wih, bih, Whh, bhh
        Wih = (const float*)d_in[6]; bih = (const float*)d_in[7];
        Whh = (const float*)d_in[8]; bhh = (const float*)d_in[9];
    } else {                           // signature order: Wih, Whh, bih, bhh
        Wih = (const float*)d_in[6]; Whh = (const float*)d_in[7];
        bih = (const float*)d_in[8]; bhh = (const float*)d_in[9];
    }
    const float* W2 = (const float*)d_in[10];
    const float* b2 = (const float*)d_in[11];
    const float* W3 = (const float*)d_in[12];
    const float* b3 = (const float*)d_in[13];

    float* out    = (float*)d_out;
    float* sample = out;                                  // [512,30]
    float* states = out + (size_t)B_DIM * S_DIM;          // [256,512,200]
    float* posts  = states + (size_t)T_STEPS * B_DIM * M_DIM; // [256,512,60]

    float* Xbuf; cudaGetSymbolAddress((void**)&Xbuf, g_X);
    float* GXbuf; cudaGetSymbolAddress((void**)&GXbuf, g_GX);

    // K1: X = elu([embed,action] @ W1^T + b1)   [131072,263]x[263,200]
    gemm_kernel<1, 1><<<dim3(TB / GBM, 4), 256>>>(
        embed, action, EA_DIM, E_DIM, W1, b1, Xbuf, H_DIM);

    // K2: GX = X @ Wih^T + bih                  [131072,200]x[200,600]
    gemm_kernel<0, 0><<<dim3(TB / GBM, 10), 256>>>(
        Xbuf, nullptr, H_DIM, 0, Wih, bih, GXbuf, G3);

    // K3: recurrent scan -> states
    init_flags_kernel<<<1, 128>>>();
    cudaFuncSetAttribute(scan_kernel,
                         cudaFuncAttributeMaxDynamicSharedMemorySize,
                         SC_SMEM_FLOATS * (int)sizeof(float));
    scan_kernel<<<SC_C * SC_R, SC_THREADS, SC_SMEM_FLOATS * sizeof(float)>>>(
        GXbuf, Whh, bhh, in_state, reset, states);

    // K4: P1 = elu(states @ W2^T + b2)  (reuse g_X)
    gemm_kernel<1, 0><<<dim3(TB / GBM, 4), 256>>>(
        states, nullptr, M_DIM, 0, W2, b2, Xbuf, H_DIM);

    // K5: posts = P1 @ W3^T + b3
    gemm_kernel<0, 0><<<dim3(TB / GBM, 1), 256>>>(
        Xbuf, nullptr, H_DIM, 0, W3, b3, posts, 2 * S_DIM);

    // K6: sample from posts[-1] with partitionable-threefry noise
    const float* posts_last = posts + (size_t)(T_STEPS - 1) * B_DIM * 2 * S_DIM;
    sample_kernel<<<(B_DIM * S_DIM + 255) / 256, 256>>>(posts_last, sample);
}